// round 13
// baseline (speedup 1.0000x reference)
#include <cuda_runtime.h>
#include <cuda_fp16.h>

// Problem dims (fixed for this problem instance)
#define B_  2048
#define T_  512
#define I_  58      // input features
#define H_  23      // hidden
#define G_  69      // 3*H gate rows
#define GP_ 72      // padded gate dim
#define KP_ 64      // padded K for tf32 mma (8 k-frags of 8)
#define MT_ 256     // rows per xproj block

// Scratch for x-projection, fp16: [B][T][GP_] + 4-row pad so the scan's
// unconditional prefetch tail over-read stays in-bounds (values unused).
__device__ __half g_xg[(size_t)B_ * T_ * GP_ + 4 * GP_];

// ---------------------------------------------------------------------------
// Helpers
// ---------------------------------------------------------------------------
__device__ __forceinline__ unsigned cvt_tf32(float f) {
    unsigned u;
    asm("cvt.rna.tf32.f32 %0, %1;" : "=r"(u) : "f"(f));
    return u;
}
__device__ __forceinline__ unsigned long long pack2(float lo, float hi) {
    unsigned long long r;
    asm("mov.b64 %0, {%1, %2};" : "=l"(r) : "f"(lo), "f"(hi));
    return r;
}
__device__ __forceinline__ void unpack2(unsigned long long v, float& lo, float& hi) {
    asm("mov.b64 {%0, %1}, %2;" : "=f"(lo), "=f"(hi) : "l"(v));
}
// Packed dual-FMA (Blackwell f32x2)
__device__ __forceinline__ unsigned long long ffma2(unsigned long long a,
                                                    unsigned long long b,
                                                    unsigned long long c) {
    unsigned long long d;
    asm("fma.rn.f32x2 %0, %1, %2, %3;" : "=l"(d) : "l"(a), "l"(b), "l"(c));
    return d;
}
__device__ __forceinline__ unsigned long long add2(unsigned long long a,
                                                   unsigned long long b) {
    unsigned long long d;
    asm("add.rn.f32x2 %0, %1, %2;" : "=l"(d) : "l"(a), "l"(b));
    return d;
}
// Single-op MUFU tanh (sm_75+) — recurrence damps the ~5e-4 approx err (measured)
__device__ __forceinline__ float mtanh(float x) {
    float r;
    asm("tanh.approx.f32 %0, %1;" : "=f"(r) : "f"(x));
    return r;
}

// ---------------------------------------------------------------------------
// Kernel 1: x-projection GEMM (tf32 mma.sync), A staged in smem via FLAT
//   float4 copy (no per-element index math — scatter staging was the R10
//   regression). Mainloop reads A with conflict-free LDS.32 + cvt.
//   xg[b][t][g] = fp16( task[b][t]·W_ih^T + b_ih ),  row m = b*T + t.
// ---------------------------------------------------------------------------
__global__ void __launch_bounds__(256, 2)
xproj_kernel(const float* __restrict__ task,
             const float* __restrict__ Wih,
             const float* __restrict__ bih)
{
    __shared__ float    As[MT_ * I_];    // 256x58 fp32 flat (59392 B)
    __shared__ unsigned Bsh[KP_][GP_];   // tf32 bits: Bsh[k][n] = Wih[n][k]
    __shared__ float    bias[GP_];

    const int tid = threadIdx.x;

    // Stage W (transposed tf32, zero-padded) + bias
    for (int idx = tid; idx < KP_ * GP_; idx += 256) {
        int k = idx / GP_, n = idx % GP_;
        float v = (k < I_ && n < G_) ? Wih[n * I_ + k] : 0.0f;
        Bsh[k][n] = cvt_tf32(v);
    }
    if (tid < GP_) bias[tid] = (tid < G_) ? bih[tid] : 0.0f;

    // Stage A tile: flat float4 copy, zero index arithmetic.
    // 256 rows x 58 fp32 = 14848 floats = 3712 float4 (tile start 16B-aligned:
    // 256*58*4 = 59392 B per block).
    {
        const float4* t4 = reinterpret_cast<const float4*>(
            task + (size_t)blockIdx.x * (MT_ * I_));
        float4* a4 = reinterpret_cast<float4*>(As);
#pragma unroll
        for (int it = 0; it < 15; it++) {
            int idx = tid + it * 256;
            if (idx < (MT_ * I_) / 4) a4[idx] = t4[idx];
        }
    }
    __syncthreads();

    const int warp = tid >> 5;
    const int lane = tid & 31;
    const int qr = lane >> 2;   // groupID (0..7)
    const int qc = lane & 3;    // tid-in-group (0..3)
    const int rw = warp * 32;   // warp row base within tile

    float acc[2][9][4];
#pragma unroll
    for (int mt = 0; mt < 2; mt++)
#pragma unroll
        for (int nt = 0; nt < 9; nt++)
#pragma unroll
            for (int i = 0; i < 4; i++) acc[mt][nt][i] = 0.0f;

#pragma unroll
    for (int kf = 0; kf < 8; kf++) {
        const int k0 = kf * 8;
        unsigned bfr[9][2];
#pragma unroll
        for (int nt = 0; nt < 9; nt++) {
            bfr[nt][0] = Bsh[k0 + qc][nt * 8 + qr];
            bfr[nt][1] = Bsh[k0 + qc + 4][nt * 8 + qr];
        }
        const int c0 = k0 + qc;
        const int c1 = c0 + 4;
#pragma unroll
        for (int mt = 0; mt < 2; mt++) {
            const int r0 = rw + mt * 16 + qr;   // rows r0, r0+8
            const float* ar0 = As + r0 * I_;
            const float* ar1 = ar0 + 8 * I_;
            unsigned a0 = (c0 < I_) ? cvt_tf32(ar0[c0]) : 0u;
            unsigned a1 = (c0 < I_) ? cvt_tf32(ar1[c0]) : 0u;
            unsigned a2 = (c1 < I_) ? cvt_tf32(ar0[c1]) : 0u;
            unsigned a3 = (c1 < I_) ? cvt_tf32(ar1[c1]) : 0u;
#pragma unroll
            for (int nt = 0; nt < 9; nt++) {
                asm volatile(
                    "mma.sync.aligned.m16n8k8.row.col.f32.tf32.tf32.f32 "
                    "{%0,%1,%2,%3}, {%4,%5,%6,%7}, {%8,%9}, {%0,%1,%2,%3};"
                    : "+f"(acc[mt][nt][0]), "+f"(acc[mt][nt][1]),
                      "+f"(acc[mt][nt][2]), "+f"(acc[mt][nt][3])
                    : "r"(a0), "r"(a1), "r"(a2), "r"(a3),
                      "r"(bfr[nt][0]), "r"(bfr[nt][1]));
            }
        }
    }

    // Epilogue: bias add, fp16 convert, contiguous 144B rows
#pragma unroll
    for (int mt = 0; mt < 2; mt++) {
#pragma unroll
        for (int half = 0; half < 2; half++) {
            const int m = blockIdx.x * MT_ + rw + mt * 16 + qr + half * 8;
            __half* orow = g_xg + (size_t)m * GP_;
#pragma unroll
            for (int nt = 0; nt < 9; nt++) {
                const int n = nt * 8 + qc * 2;
                __half2 v = __floats2half2_rn(
                    acc[mt][nt][half * 2 + 0] + bias[n],
                    acc[mt][nt][half * 2 + 1] + bias[n + 1]);
                *reinterpret_cast<__half2*>(orow + n) = v;
            }
        }
    }
}

// ---------------------------------------------------------------------------
// Kernel 2: GRU scan. One warp per batch; MUFU-tanh activations (measured).
//   2-step manual unroll: static buffer parity, unconditional prefetch
//   advance (array padded), halved loop bookkeeping — the loop is
//   issue-slot-limited, so fewer slots/step => shorter step period.
// ---------------------------------------------------------------------------
#define SCAN_STEP(PB)                                                          \
    {                                                                          \
        const float xr = xr0, xz = xz0, xn = xn0;                              \
        xr0 = xr1; xz0 = xz1; xn0 = xn1;                                       \
        xr1 = __half2float(pf[l]);                                             \
        xz1 = __half2float(pf[H_ + l]);                                        \
        xn1 = __half2float(pf[2 * H_ + l]);                                    \
        pf += GP_;                                                             \
        unsigned long long ar0 = br0, ar1 = 0ull;                              \
        unsigned long long az0 = bz0, az1 = 0ull;                              \
        unsigned long long an0 = bn0, an1 = 0ull;                              \
        _Pragma("unroll")                                                      \
        for (int jj = 0; jj < 3; jj++) {                                       \
            ar0 = ffma2(wr[2 * jj],     h4[jj].x, ar0);                        \
            az0 = ffma2(wz[2 * jj],     h4[jj].x, az0);                        \
            an0 = ffma2(wn[2 * jj],     h4[jj].x, an0);                        \
            ar0 = ffma2(wr[2 * jj + 1], h4[jj].y, ar0);                        \
            az0 = ffma2(wz[2 * jj + 1], h4[jj].y, az0);                        \
            an0 = ffma2(wn[2 * jj + 1], h4[jj].y, an0);                        \
        }                                                                      \
        _Pragma("unroll")                                                      \
        for (int jj = 3; jj < 6; jj++) {                                       \
            ar1 = ffma2(wr[2 * jj],     h4[jj].x, ar1);                        \
            az1 = ffma2(wz[2 * jj],     h4[jj].x, az1);                        \
            an1 = ffma2(wn[2 * jj],     h4[jj].x, an1);                        \
            ar1 = ffma2(wr[2 * jj + 1], h4[jj].y, ar1);                        \
            az1 = ffma2(wz[2 * jj + 1], h4[jj].y, az1);                        \
            an1 = ffma2(wn[2 * jj + 1], h4[jj].y, an1);                        \
        }                                                                      \
        float hrx, hry, hzx, hzy, hnx, hny;                                    \
        unpack2(add2(ar0, ar1), hrx, hry);                                     \
        unpack2(add2(az0, az1), hzx, hzy);                                     \
        unpack2(add2(an0, an1), hnx, hny);                                     \
        const float r  = fmaf(0.5f, mtanh(0.5f * (xr + (hrx + hry))), 0.5f);   \
        const float tz = mtanh(0.5f * (xz + (hzx + hzy)));                     \
        const float n  = mtanh(fmaf(r, hnx + hny, xn));                        \
        const float hnew = fmaf(0.5f * tz, hmine - n, 0.5f * (hmine + n));     \
        if (act) *op = fmaf(piw, hnew, pib);                                   \
        op += H_;                                                              \
        hmine = hnew;                                                          \
        if (act) hsh[PB][lane] = hnew;                                         \
        __syncwarp();                                                          \
        _Pragma("unroll")                                                      \
        for (int j = 0; j < 6; j++)                                            \
            h4[j] = *reinterpret_cast<const ulonglong2*>(&hsh[PB][4 * j]);     \
    }

__global__ void __launch_bounds__(32)
scan_kernel(const float* __restrict__ Whh,
            const float* __restrict__ bhh,
            const float* __restrict__ piw_g,
            const float* __restrict__ pib_g,
            float* __restrict__ out)
{
    const int lane  = threadIdx.x;
    const int batch = blockIdx.x;
    const bool act  = lane < H_;
    const int l     = act ? lane : 0;

    __shared__ __align__(16) float hsh[2][24];   // double-buffered h (pad j=23)

    // W_hh rows for this lane as j-pairs (j=23 padded with 0)
    unsigned long long wr[12], wz[12], wn[12];
#pragma unroll
    for (int j = 0; j < 12; j++) {
        const int j0 = 2 * j, j1 = 2 * j + 1;
        float r1 = (j1 < H_) ? Whh[(size_t)l * H_ + j1] : 0.0f;
        float z1 = (j1 < H_) ? Whh[(size_t)(H_ + l) * H_ + j1] : 0.0f;
        float n1 = (j1 < H_) ? Whh[(size_t)(2 * H_ + l) * H_ + j1] : 0.0f;
        wr[j] = pack2(Whh[(size_t)l * H_ + j0], r1);
        wz[j] = pack2(Whh[(size_t)(H_ + l) * H_ + j0], z1);
        wn[j] = pack2(Whh[(size_t)(2 * H_ + l) * H_ + j0], n1);
    }
    const unsigned long long br0 = pack2(bhh[l], 0.0f);
    const unsigned long long bz0 = pack2(bhh[H_ + l], 0.0f);
    const unsigned long long bn0 = pack2(bhh[2 * H_ + l], 0.0f);
    const float piw = piw_g[l], pib = pib_g[l];

    ulonglong2 h4[6];      // 24 h values as 6x (f32x2, f32x2)
#pragma unroll
    for (int j = 0; j < 6; j++) { h4[j].x = 0ull; h4[j].y = 0ull; }
    float hmine = 0.0f;
    if (lane < 24) { hsh[0][lane] = 0.0f; hsh[1][lane] = 0.0f; }
    __syncwarp();

    const __half* xb = g_xg + (size_t)batch * T_ * GP_;
    float*        op = out + (size_t)batch * T_ * H_ + lane;

    // Prefetch pipeline, distance 2 (tail over-reads land in pad / next batch;
    // those values are shifted but never consumed)
    float xr0 = __half2float(xb[l]);
    float xz0 = __half2float(xb[H_ + l]);
    float xn0 = __half2float(xb[2 * H_ + l]);
    float xr1 = __half2float(xb[GP_ + l]);
    float xz1 = __half2float(xb[GP_ + H_ + l]);
    float xn1 = __half2float(xb[GP_ + 2 * H_ + l]);
    const __half* pf = xb + 2 * GP_;

    for (int t = 0; t < T_; t += 2) {
        SCAN_STEP(0)
        SCAN_STEP(1)
    }

    // hidden = hT
    if (act)
        out[(size_t)B_ * T_ * H_ + (size_t)batch * H_ + lane] = hmine;
}

// ---------------------------------------------------------------------------
extern "C" void kernel_launch(void* const* d_in, const int* in_sizes, int n_in,
                              void* d_out, int out_size)
{
    const float* task = (const float*)d_in[0];   // (2048, 512, 58)
    const float* Wih  = (const float*)d_in[1];   // (69, 58)
    const float* Whh  = (const float*)d_in[2];   // (69, 23)
    const float* bih  = (const float*)d_in[3];   // (69,)
    const float* bhh  = (const float*)d_in[4];   // (69,)
    const float* piw  = (const float*)d_in[5];   // (23,)
    const float* pib  = (const float*)d_in[6];   // (23,)
    float* out = (float*)d_out;                  // action_pred (2048,512,23) ++ hidden (1,2048,23)

    xproj_kernel<<<(B_ * T_) / MT_, 256>>>(task, Wih, bih);
    scan_kernel<<<B_, 32>>>(Whh, bhh, piw, pib, out);
}